// round 1
// baseline (speedup 1.0000x reference)
#include <cuda_runtime.h>
#include <math.h>

#define B_    1024
#define DIN_  343
#define DH_   342
#define H_    512
#define DOUT_ 311
#define K0P_  1376   // 4 * 344  (342 feats + 1 bias slot + 1 pad per control)
#define K1P_  2064   // 4*512 h-slots + 4 bias slots + 12 pad
#define NP2_  320    // DOUT padded to tile

// ---- scratch (static device globals; allocation-free rule) ----
__device__ float g_z0[B_ * K0P_];
__device__ float g_z1[B_ * K1P_];
__device__ float g_z2[B_ * K1P_];
__device__ float g_w0[H_  * K0P_];
__device__ float g_w1[H_  * K1P_];
__device__ float g_w2[NP2_ * K1P_];
__device__ float g_coef[B_ * 4];

__device__ __forceinline__ float elu1(float v) {
    return v > 0.0f ? v : expm1f(v);
}

// ---- per-sample cubic coefficients + bias slots of z1/z2 ----
__global__ void k_coef(const float* __restrict__ x) {
    int b = blockIdx.x * blockDim.x + threadIdx.x;
    if (b >= B_) return;
    float ps = 4.0f * x[b * DIN_ + (DIN_ - 1)];
    float mu = ps - floorf(ps);
    int   k1 = ((int)ps) & 3;
    float m2 = mu * mu, m3 = m2 * mu;
    float a0 = -0.5f * m3 +        m2 - 0.5f * mu;
    float a1 =  1.5f * m3 - 2.5f * m2 + 1.0f;
    float a2 = -1.5f * m3 + 2.0f * m2 + 0.5f * mu;
    float a3 =  0.5f * m3 - 0.5f * m2;
    float c[4];
    c[(k1 + 3) & 3] = a0;
    c[k1]           = a1;
    c[(k1 + 1) & 3] = a2;
    c[(k1 + 2) & 3] = a3;
#pragma unroll
    for (int j = 0; j < 4; j++) {
        g_coef[b * 4 + j] = c[j];
        g_z1[b * K1P_ + 2048 + j] = c[j];
        g_z2[b * K1P_ + 2048 + j] = c[j];
    }
#pragma unroll
    for (int j = 2052; j < K1P_; j++) {
        g_z1[b * K1P_ + j] = 0.0f;
        g_z2[b * K1P_ + j] = 0.0f;
    }
}

// ---- z0[b][c*344 + i] = coef_c * x[b][i]; bias slot at i=342; pad at 343 ----
__global__ void k_z0(const float* __restrict__ x) {
    int b = blockIdx.x;
    float c0 = g_coef[b * 4 + 0], c1 = g_coef[b * 4 + 1];
    float c2 = g_coef[b * 4 + 2], c3 = g_coef[b * 4 + 3];
    float* z = &g_z0[b * K0P_];
    for (int i = threadIdx.x; i < DH_; i += blockDim.x) {
        float v = x[b * DIN_ + i];
        z[0 * 344 + i] = c0 * v;
        z[1 * 344 + i] = c1 * v;
        z[2 * 344 + i] = c2 * v;
        z[3 * 344 + i] = c3 * v;
    }
    if (threadIdx.x < 4) {
        int c = threadIdx.x;
        float cc = g_coef[b * 4 + c];
        z[c * 344 + 342] = cc;
        z[c * 344 + 343] = 0.0f;
    }
}

// ---- concatenated weight builders ----
__global__ void k_w0(const float* __restrict__ W0, const float* __restrict__ b0) {
    int o = blockIdx.x;  // 0..511
    for (int j = threadIdx.x; j < K0P_; j += blockDim.x) {
        int c = j / 344;
        int i = j - c * 344;
        float v;
        if (i < DH_)        v = W0[(c * H_ + o) * DH_ + i];
        else if (i == DH_)  v = b0[c * H_ + o];
        else                v = 0.0f;
        g_w0[o * K0P_ + j] = v;
    }
}

__global__ void k_w1(const float* __restrict__ W1, const float* __restrict__ b1) {
    int o = blockIdx.x;  // 0..511
    for (int j = threadIdx.x; j < K1P_; j += blockDim.x) {
        float v;
        if (j < 2048) {
            int c = j >> 9, i = j & 511;
            v = W1[(c * H_ + o) * H_ + i];
        } else if (j < 2052) {
            v = b1[(j - 2048) * H_ + o];
        } else v = 0.0f;
        g_w1[o * K1P_ + j] = v;
    }
}

__global__ void k_w2(const float* __restrict__ W2, const float* __restrict__ b2) {
    int o = blockIdx.x;  // 0..319
    for (int j = threadIdx.x; j < K1P_; j += blockDim.x) {
        float v = 0.0f;
        if (o < DOUT_) {
            if (j < 2048) {
                int c = j >> 9, i = j & 511;
                v = W2[(c * DOUT_ + o) * H_ + i];
            } else if (j < 2052) {
                v = b2[(j - 2048) * DOUT_ + o];
            }
        }
        g_w2[o * K1P_ + j] = v;
    }
}

// ---- fused GEMM: C = Z @ Wcat^T ; epilogue ELU + scatter into next z, or final store
// LAYER: 0 -> z0 x w0 -> z1 ; 1 -> z1 x w1 -> z2 ; 2 -> z2 x w2 -> out
template <int LAYER>
__global__ void __launch_bounds__(256, 2) k_gemm(float* __restrict__ out_final) {
    constexpr int KP = (LAYER == 0) ? K0P_ : K1P_;
    const float* __restrict__ A  = (LAYER == 0) ? g_z0 : (LAYER == 1 ? g_z1 : g_z2);
    const float* __restrict__ Bm = (LAYER == 0) ? g_w0 : (LAYER == 1 ? g_w1 : g_w2);

    __shared__ float As[16][68];
    __shared__ float Bs[16][68];

    const int t  = threadIdx.x;
    const int tx = t & 15, ty = t >> 4;
    const int bm = blockIdx.y * 64, bn = blockIdx.x * 64;
    const int lr = t >> 2, lq = t & 3;

    const float* Ap = A  + (size_t)(bm + lr) * KP + lq * 4;
    const float* Bp = Bm + (size_t)(bn + lr) * KP + lq * 4;

    float acc[4][4] = {};

    float4 av = *(const float4*)(Ap);
    float4 bv = *(const float4*)(Bp);

#pragma unroll 1
    for (int k0 = 0; k0 < KP; k0 += 16) {
        __syncthreads();
        As[lq * 4 + 0][lr] = av.x; As[lq * 4 + 1][lr] = av.y;
        As[lq * 4 + 2][lr] = av.z; As[lq * 4 + 3][lr] = av.w;
        Bs[lq * 4 + 0][lr] = bv.x; Bs[lq * 4 + 1][lr] = bv.y;
        Bs[lq * 4 + 2][lr] = bv.z; Bs[lq * 4 + 3][lr] = bv.w;
        __syncthreads();
        if (k0 + 16 < KP) {
            av = *(const float4*)(Ap + k0 + 16);
            bv = *(const float4*)(Bp + k0 + 16);
        }
#pragma unroll
        for (int kk = 0; kk < 16; kk++) {
            float4 a = *(const float4*)&As[kk][ty * 4];
            float4 b = *(const float4*)&Bs[kk][tx * 4];
            acc[0][0] += a.x * b.x; acc[0][1] += a.x * b.y;
            acc[0][2] += a.x * b.z; acc[0][3] += a.x * b.w;
            acc[1][0] += a.y * b.x; acc[1][1] += a.y * b.y;
            acc[1][2] += a.y * b.z; acc[1][3] += a.y * b.w;
            acc[2][0] += a.z * b.x; acc[2][1] += a.z * b.y;
            acc[2][2] += a.z * b.z; acc[2][3] += a.z * b.w;
            acc[3][0] += a.w * b.x; acc[3][1] += a.w * b.y;
            acc[3][2] += a.w * b.z; acc[3][3] += a.w * b.w;
        }
    }

    if (LAYER < 2) {
        float* __restrict__ zn = (LAYER == 0) ? g_z1 : g_z2;
#pragma unroll
        for (int i = 0; i < 4; i++) {
            int m = bm + ty * 4 + i;
            float h0 = elu1(acc[i][0]);
            float h1 = elu1(acc[i][1]);
            float h2 = elu1(acc[i][2]);
            float h3 = elu1(acc[i][3]);
            float4 cf = *(const float4*)&g_coef[m * 4];
            float cfs[4] = {cf.x, cf.y, cf.z, cf.w};
#pragma unroll
            for (int c = 0; c < 4; c++) {
                float4 sv = make_float4(cfs[c] * h0, cfs[c] * h1,
                                        cfs[c] * h2, cfs[c] * h3);
                *(float4*)&zn[(size_t)m * K1P_ + c * 512 + bn + tx * 4] = sv;
            }
        }
    } else {
#pragma unroll
        for (int i = 0; i < 4; i++) {
            int m = bm + ty * 4 + i;
#pragma unroll
            for (int j = 0; j < 4; j++) {
                int o = bn + tx * 4 + j;
                if (o < DOUT_) out_final[(size_t)m * DOUT_ + o] = acc[i][j];
            }
        }
    }
}

extern "C" void kernel_launch(void* const* d_in, const int* in_sizes, int n_in,
                              void* d_out, int out_size) {
    const float* x  = (const float*)d_in[0];
    const float* W0 = (const float*)d_in[1];
    const float* W1 = (const float*)d_in[2];
    const float* W2 = (const float*)d_in[3];
    const float* b0 = (const float*)d_in[4];
    const float* b1 = (const float*)d_in[5];
    const float* b2 = (const float*)d_in[6];
    float* out = (float*)d_out;

    k_coef<<<4, 256>>>(x);
    k_w0<<<512, 256>>>(W0, b0);
    k_w1<<<512, 256>>>(W1, b1);
    k_w2<<<NP2_, 256>>>(W2, b2);
    k_z0<<<B_, 128>>>(x);

    k_gemm<0><<<dim3(8, 16), 256>>>(out);
    k_gemm<1><<<dim3(8, 16), 256>>>(out);
    k_gemm<2><<<dim3(5, 16), 256>>>(out);
}

// round 3
// speedup vs baseline: 1.1039x; 1.1039x over previous
#include <cuda_runtime.h>
#include <cstdint>
#include <math.h>

#define B_    1024
#define DIN_  343
#define DH_   342
#define H_    512
#define DOUT_ 311
#define NP2_  320

#define S0_   352            // per-control K stride, layer 0
#define K0P_  1408           // 4 * 352  (44 chunks of 32)
#define S1_   528            // 512 h + 1 bias + 15 pad
#define K1P_  2112           // 4 * 528  (66 chunks of 32)

// ---- scratch ----
__device__ float g_z0[B_ * K0P_];
__device__ float g_z1[B_ * K1P_];
__device__ float g_z2[B_ * K1P_];
__device__ float g_w0[H_ * K0P_];
__device__ float g_w1[H_ * K1P_];
__device__ float g_w2[NP2_ * K1P_];
__device__ float g_coef[B_ * 4];

// ---------------- helpers ----------------
__device__ __forceinline__ float to_tf32(float v) {
    uint32_t o; asm("cvt.rna.tf32.f32 %0, %1;" : "=r"(o) : "f"(v));
    return __uint_as_float(o);
}
__device__ __forceinline__ float elu1(float v) { return v > 0.0f ? v : expm1f(v); }

__device__ __forceinline__ uint32_t smem_u32(const void* p) {
    uint32_t a;
    asm("{ .reg .u64 t; cvta.to.shared.u64 t, %1; cvt.u32.u64 %0, t; }" : "=r"(a) : "l"(p));
    return a;
}
__device__ __forceinline__ void cp16(uint32_t dst, const float* src) {
    asm volatile("cp.async.cg.shared.global [%0], [%1], 16;" :: "r"(dst), "l"(src) : "memory");
}
__device__ __forceinline__ void cp_commit() { asm volatile("cp.async.commit_group;" ::: "memory"); }
template <int N> __device__ __forceinline__ void cp_wait() {
    asm volatile("cp.async.wait_group %0;" :: "n"(N) : "memory");
}
__device__ __forceinline__ void ldsm4(uint32_t* r, uint32_t addr) {
    asm volatile("ldmatrix.sync.aligned.m8n8.x4.shared.b16 {%0,%1,%2,%3}, [%4];"
                 : "=r"(r[0]), "=r"(r[1]), "=r"(r[2]), "=r"(r[3]) : "r"(addr));
}
__device__ __forceinline__ void mma8(float* c, const uint32_t* a, uint32_t b0, uint32_t b1) {
    asm volatile(
        "mma.sync.aligned.m16n8k8.row.col.f32.tf32.tf32.f32 "
        "{%0,%1,%2,%3}, {%4,%5,%6,%7}, {%8,%9}, {%0,%1,%2,%3};"
        : "+f"(c[0]), "+f"(c[1]), "+f"(c[2]), "+f"(c[3])
        : "r"(a[0]), "r"(a[1]), "r"(a[2]), "r"(a[3]), "r"(b0), "r"(b1));
}

// ---------------- prep kernels ----------------
__global__ void k_coef(const float* __restrict__ x) {
    int b = blockIdx.x * blockDim.x + threadIdx.x;
    if (b >= B_) return;
    float ps = 4.0f * x[b * DIN_ + (DIN_ - 1)];
    float mu = ps - floorf(ps);
    int   k1 = ((int)ps) & 3;
    float m2 = mu * mu, m3 = m2 * mu;
    float a0 = -0.5f * m3 +        m2 - 0.5f * mu;
    float a1 =  1.5f * m3 - 2.5f * m2 + 1.0f;
    float a2 = -1.5f * m3 + 2.0f * m2 + 0.5f * mu;
    float a3 =  0.5f * m3 - 0.5f * m2;
    float c[4];
    c[(k1 + 3) & 3] = a0;
    c[k1]           = a1;
    c[(k1 + 1) & 3] = a2;
    c[(k1 + 2) & 3] = a3;
#pragma unroll
    for (int j = 0; j < 4; j++) {
        g_coef[b * 4 + j] = c[j];
        float ct = to_tf32(c[j]);
        size_t base = (size_t)b * K1P_ + j * S1_;
        g_z1[base + 512] = ct;
        g_z2[base + 512] = ct;
#pragma unroll
        for (int p = 513; p < S1_; p++) { g_z1[base + p] = 0.0f; g_z2[base + p] = 0.0f; }
    }
}

__global__ void k_z0(const float* __restrict__ x) {
    int b = blockIdx.x;
    float4 cf = *(const float4*)&g_coef[b * 4];
    float cc[4] = {cf.x, cf.y, cf.z, cf.w};
    const float* xr = x + (size_t)b * DIN_;
    float* z = g_z0 + (size_t)b * K0P_;
    for (int i = threadIdx.x; i < S0_; i += blockDim.x) {
        float v0, v1, v2, v3;
        if (i < DH_) {
            float v = xr[i];
            v0 = to_tf32(cc[0] * v); v1 = to_tf32(cc[1] * v);
            v2 = to_tf32(cc[2] * v); v3 = to_tf32(cc[3] * v);
        } else if (i == DH_) {
            v0 = to_tf32(cc[0]); v1 = to_tf32(cc[1]);
            v2 = to_tf32(cc[2]); v3 = to_tf32(cc[3]);
        } else { v0 = v1 = v2 = v3 = 0.0f; }
        z[0 * S0_ + i] = v0; z[1 * S0_ + i] = v1;
        z[2 * S0_ + i] = v2; z[3 * S0_ + i] = v3;
    }
}

__global__ void k_wall(const float* __restrict__ W0, const float* __restrict__ W1,
                       const float* __restrict__ W2, const float* __restrict__ b0,
                       const float* __restrict__ b1, const float* __restrict__ b2) {
    int blk = blockIdx.x;
    if (blk < 512) {
        int o = blk;
#pragma unroll
        for (int c = 0; c < 4; c++) {
            const float* src = W0 + ((size_t)(c * H_ + o)) * DH_;
            float bias = b0[c * H_ + o];
            float* dst = g_w0 + (size_t)o * K0P_ + c * S0_;
            for (int i = threadIdx.x; i < S0_; i += blockDim.x) {
                float v = (i < DH_) ? src[i] : (i == DH_ ? bias : 0.0f);
                dst[i] = to_tf32(v);
            }
        }
    } else if (blk < 1024) {
        int o = blk - 512;
#pragma unroll
        for (int c = 0; c < 4; c++) {
            const float* src = W1 + ((size_t)(c * H_ + o)) * H_;
            float bias = b1[c * H_ + o];
            float* dst = g_w1 + (size_t)o * K1P_ + c * S1_;
            for (int i = threadIdx.x; i < S1_; i += blockDim.x) {
                float v = (i < H_) ? src[i] : (i == H_ ? bias : 0.0f);
                dst[i] = to_tf32(v);
            }
        }
    } else {
        int o = blk - 1024;
        bool valid = (o < DOUT_);
#pragma unroll
        for (int c = 0; c < 4; c++) {
            const float* src = W2 + ((size_t)(c * DOUT_ + o)) * H_;
            float bias = valid ? b2[c * DOUT_ + o] : 0.0f;
            float* dst = g_w2 + (size_t)o * K1P_ + c * S1_;
            for (int i = threadIdx.x; i < S1_; i += blockDim.x) {
                float v = 0.0f;
                if (valid) v = (i < H_) ? src[i] : (i == H_ ? bias : 0.0f);
                dst[i] = to_tf32(v);
            }
        }
    }
}

// ---------------- tf32 mma.sync GEMM ----------------
// CTA 64x64, 4 warps (2Mx2N), warp 32x32, k-chunk 32, 2-stage cp.async.
// SMEM layout per stage: A then B; each as 8x8 grid of (8row x 4col fp32)
// matrices, 128B per matrix, rows XOR-swizzled by k4.

__device__ __forceinline__ void fill_stage(uint32_t sdst, const float* __restrict__ A,
                                           const float* __restrict__ Bw,
                                           int bm, int bn, int KP, int k0, int t) {
#pragma unroll
    for (int j = 0; j < 4; j++) {
        int f = t + j * 128;
        int m = f >> 3, k4 = f & 7;
        uint32_t off = (uint32_t)((((m >> 3) * 8 + k4) * 128) + (((m & 7) ^ k4) * 16));
        cp16(sdst + off, A + (size_t)(bm + m) * KP + k0 + k4 * 4);
        cp16(sdst + 8192u + off, Bw + (size_t)(bn + m) * KP + k0 + k4 * 4);
    }
}

template <int LAYER>
__global__ void __launch_bounds__(128) k_gemm(float* __restrict__ out_final) {
    constexpr int KP  = (LAYER == 0) ? K0P_ : K1P_;
    constexpr int NIT = KP / 32;
    const float* __restrict__ A  = (LAYER == 0) ? g_z0 : (LAYER == 1 ? g_z1 : g_z2);
    const float* __restrict__ Bw = (LAYER == 0) ? g_w0 : (LAYER == 1 ? g_w1 : g_w2);

    __shared__ float smem[2][4096];   // [stage][A 64x32 | B 64x32]
    uint32_t sbase = smem_u32(smem);

    const int t = threadIdx.x, lane = t & 31, wid = t >> 5;
    const int wm = (wid >> 1) * 32, wn = (wid & 1) * 32;
    const int bm = blockIdx.y * 64, bn = blockIdx.x * 64;
    const int g = lane >> 3, r = lane & 7;
    const int ga = g & 1, gb = g >> 1;
    const int wm8 = wm >> 3, wn8 = wn >> 3;

    float acc[2][4][4] = {};

    fill_stage(sbase, A, Bw, bm, bn, KP, 0, t);
    cp_commit();

#pragma unroll 1
    for (int it = 0; it < NIT; it++) {
        int s = it & 1;
        if (it + 1 < NIT) {
            fill_stage(sbase + (s ^ 1) * 16384u, A, Bw, bm, bn, KP, (it + 1) * 32, t);
            cp_commit();
            cp_wait<1>();
        } else {
            cp_wait<0>();
        }
        __syncthreads();

        uint32_t sa = sbase + (uint32_t)s * 16384u;
        uint32_t sbB = sa + 8192u;
#pragma unroll
        for (int ki2 = 0; ki2 < 4; ki2++) {
            int k4a = ki2 * 2 + gb;
            int k4b = ki2 * 2 + ga;
            uint32_t a0[4], a1[4], bb[8];
            ldsm4(a0, sa + (uint32_t)((((wm8 + ga) * 8 + k4a) * 128) + ((r ^ k4a) * 16)));
            ldsm4(a1, sa + (uint32_t)((((wm8 + 2 + ga) * 8 + k4a) * 128) + ((r ^ k4a) * 16)));
            ldsm4(bb,     sbB + (uint32_t)((((wn8 + gb) * 8 + k4b) * 128) + ((r ^ k4b) * 16)));
            ldsm4(bb + 4, sbB + (uint32_t)((((wn8 + 2 + gb) * 8 + k4b) * 128) + ((r ^ k4b) * 16)));
            mma8(acc[0][0], a0, bb[0], bb[1]);
            mma8(acc[0][1], a0, bb[2], bb[3]);
            mma8(acc[0][2], a0, bb[4], bb[5]);
            mma8(acc[0][3], a0, bb[6], bb[7]);
            mma8(acc[1][0], a1, bb[0], bb[1]);
            mma8(acc[1][1], a1, bb[2], bb[3]);
            mma8(acc[1][2], a1, bb[4], bb[5]);
            mma8(acc[1][3], a1, bb[6], bb[7]);
        }
        __syncthreads();
    }

    // ---- epilogue ----
    if (LAYER < 2) {
        float* __restrict__ zn = (LAYER == 0) ? g_z1 : g_z2;
#pragma unroll
        for (int mt = 0; mt < 2; mt++) {
            int m0 = bm + wm + mt * 16 + (lane >> 2);
            int m1 = m0 + 8;
            float4 cA = *(const float4*)&g_coef[m0 * 4];
            float4 cB = *(const float4*)&g_coef[m1 * 4];
            float ca[4] = {cA.x, cA.y, cA.z, cA.w};
            float cb[4] = {cB.x, cB.y, cB.z, cB.w};
#pragma unroll
            for (int nt = 0; nt < 4; nt++) {
                int n = bn + wn + nt * 8 + (lane & 3) * 2;
                float h00 = elu1(acc[mt][nt][0]);
                float h01 = elu1(acc[mt][nt][1]);
                float h10 = elu1(acc[mt][nt][2]);
                float h11 = elu1(acc[mt][nt][3]);
#pragma unroll
                for (int ct = 0; ct < 4; ct++) {
                    float2 v0 = make_float2(to_tf32(ca[ct] * h00), to_tf32(ca[ct] * h01));
                    float2 v1 = make_float2(to_tf32(cb[ct] * h10), to_tf32(cb[ct] * h11));
                    *(float2*)&zn[(size_t)m0 * K1P_ + ct * S1_ + n] = v0;
                    *(float2*)&zn[(size_t)m1 * K1P_ + ct * S1_ + n] = v1;
                }
            }
        }
    } else {
#pragma unroll
        for (int mt = 0; mt < 2; mt++) {
            int m0 = bm + wm + mt * 16 + (lane >> 2);
            int m1 = m0 + 8;
#pragma unroll
            for (int nt = 0; nt < 4; nt++) {
                int n = bn + wn + nt * 8 + (lane & 3) * 2;
                if (n < DOUT_) {
                    out_final[(size_t)m0 * DOUT_ + n] = acc[mt][nt][0];
                    out_final[(size_t)m1 * DOUT_ + n] = acc[mt][nt][2];
                }
                if (n + 1 < DOUT_) {
                    out_final[(size_t)m0 * DOUT_ + n + 1] = acc[mt][nt][1];
                    out_final[(size_t)m1 * DOUT_ + n + 1] = acc[mt][nt][3];
                }
            }
        }
    }
}

// ---------------- launch ----------------
extern "C" void kernel_launch(void* const* d_in, const int* in_sizes, int n_in,
                              void* d_out, int out_size) {
    const float* x  = (const float*)d_in[0];
    const float* W0 = (const float*)d_in[1];
    const float* W1 = (const float*)d_in[2];
    const float* W2 = (const float*)d_in[3];
    const float* b0 = (const float*)d_in[4];
    const float* b1 = (const float*)d_in[5];
    const float* b2 = (const float*)d_in[6];
    float* out = (float*)d_out;

    k_coef<<<4, 256>>>(x);
    k_wall<<<1344, 256>>>(W0, W1, W2, b0, b1, b2);
    k_z0<<<B_, 128>>>(x);

    k_gemm<0><<<dim3(8, 16), 128>>>(nullptr);
    k_gemm<1><<<dim3(8, 16), 128>>>(nullptr);
    k_gemm<2><<<dim3(5, 16), 128>>>(out);
}

// round 4
// speedup vs baseline: 1.2564x; 1.1381x over previous
#include <cuda_runtime.h>
#include <cstdint>
#include <math.h>

#define B_    1024
#define DIN_  343
#define DH_   342
#define H_    512
#define DOUT_ 311
#define NP2_  320

#define S0_   352            // per-control K stride, layer 0
#define K0P_  1408           // 4 * 352  (44 chunks of 32)
#define S1_   528            // 512 h + 1 bias + 15 pad
#define K1P_  2112           // 4 * 528  (66 chunks of 32)

// ---- scratch ----
__device__ float g_z0[B_ * K0P_];
__device__ float g_z1[B_ * K1P_];
__device__ float g_z2[B_ * K1P_];
__device__ float g_w0[H_ * K0P_];
__device__ float g_w1[H_ * K1P_];
__device__ float g_w2[NP2_ * K1P_];
__device__ float g_coef[B_ * 4];

// ---------------- helpers ----------------
__device__ __forceinline__ float to_tf32(float v) {
    uint32_t o; asm("cvt.rna.tf32.f32 %0, %1;" : "=r"(o) : "f"(v));
    return __uint_as_float(o);
}
__device__ __forceinline__ float elu1(float v) { return v > 0.0f ? v : expm1f(v); }

__device__ __forceinline__ uint32_t smem_u32(const void* p) {
    uint32_t a;
    asm("{ .reg .u64 t; cvta.to.shared.u64 t, %1; cvt.u32.u64 %0, t; }" : "=r"(a) : "l"(p));
    return a;
}
__device__ __forceinline__ void cp16(uint32_t dst, const float* src) {
    asm volatile("cp.async.cg.shared.global [%0], [%1], 16;" :: "r"(dst), "l"(src) : "memory");
}
__device__ __forceinline__ void cp_commit() { asm volatile("cp.async.commit_group;" ::: "memory"); }
template <int N> __device__ __forceinline__ void cp_wait() {
    asm volatile("cp.async.wait_group %0;" :: "n"(N) : "memory");
}
__device__ __forceinline__ void ldsm4(uint32_t* r, uint32_t addr) {
    asm volatile("ldmatrix.sync.aligned.m8n8.x4.shared.b16 {%0,%1,%2,%3}, [%4];"
                 : "=r"(r[0]), "=r"(r[1]), "=r"(r[2]), "=r"(r[3]) : "r"(addr));
}
__device__ __forceinline__ void mma8(float* c, const uint32_t* a, uint32_t b0, uint32_t b1) {
    asm volatile(
        "mma.sync.aligned.m16n8k8.row.col.f32.tf32.tf32.f32 "
        "{%0,%1,%2,%3}, {%4,%5,%6,%7}, {%8,%9}, {%0,%1,%2,%3};"
        : "+f"(c[0]), "+f"(c[1]), "+f"(c[2]), "+f"(c[3])
        : "r"(a[0]), "r"(a[1]), "r"(a[2]), "r"(a[3]), "r"(b0), "r"(b1));
}

// ---------------- prep kernels ----------------
__global__ void k_coef(const float* __restrict__ x) {
    int b = blockIdx.x * blockDim.x + threadIdx.x;
    if (b >= B_) return;
    float ps = 4.0f * x[b * DIN_ + (DIN_ - 1)];
    float mu = ps - floorf(ps);
    int   k1 = ((int)ps) & 3;
    float m2 = mu * mu, m3 = m2 * mu;
    float a0 = -0.5f * m3 +        m2 - 0.5f * mu;
    float a1 =  1.5f * m3 - 2.5f * m2 + 1.0f;
    float a2 = -1.5f * m3 + 2.0f * m2 + 0.5f * mu;
    float a3 =  0.5f * m3 - 0.5f * m2;
    float c[4];
    c[(k1 + 3) & 3] = a0;
    c[k1]           = a1;
    c[(k1 + 1) & 3] = a2;
    c[(k1 + 2) & 3] = a3;
#pragma unroll
    for (int j = 0; j < 4; j++) {
        g_coef[b * 4 + j] = c[j];
        float ct = to_tf32(c[j]);
        size_t base = (size_t)b * K1P_ + j * S1_;
        g_z1[base + 512] = ct;
        g_z2[base + 512] = ct;
#pragma unroll
        for (int p = 513; p < S1_; p++) { g_z1[base + p] = 0.0f; g_z2[base + p] = 0.0f; }
    }
}

__global__ void k_z0(const float* __restrict__ x) {
    int b = blockIdx.x;
    float4 cf = *(const float4*)&g_coef[b * 4];
    float cc[4] = {cf.x, cf.y, cf.z, cf.w};
    const float* xr = x + (size_t)b * DIN_;
    float* z = g_z0 + (size_t)b * K0P_;
    for (int i = threadIdx.x; i < S0_; i += blockDim.x) {
        float v0, v1, v2, v3;
        if (i < DH_) {
            float v = xr[i];
            v0 = to_tf32(cc[0] * v); v1 = to_tf32(cc[1] * v);
            v2 = to_tf32(cc[2] * v); v3 = to_tf32(cc[3] * v);
        } else if (i == DH_) {
            v0 = to_tf32(cc[0]); v1 = to_tf32(cc[1]);
            v2 = to_tf32(cc[2]); v3 = to_tf32(cc[3]);
        } else { v0 = v1 = v2 = v3 = 0.0f; }
        z[0 * S0_ + i] = v0; z[1 * S0_ + i] = v1;
        z[2 * S0_ + i] = v2; z[3 * S0_ + i] = v3;
    }
}

__global__ void k_wall(const float* __restrict__ W0, const float* __restrict__ W1,
                       const float* __restrict__ W2, const float* __restrict__ b0,
                       const float* __restrict__ b1, const float* __restrict__ b2) {
    int blk = blockIdx.x;
    if (blk < 512) {
        int o = blk;
#pragma unroll
        for (int c = 0; c < 4; c++) {
            const float* src = W0 + ((size_t)(c * H_ + o)) * DH_;
            float bias = b0[c * H_ + o];
            float* dst = g_w0 + (size_t)o * K0P_ + c * S0_;
            for (int i = threadIdx.x; i < S0_; i += blockDim.x) {
                float v = (i < DH_) ? src[i] : (i == DH_ ? bias : 0.0f);
                dst[i] = to_tf32(v);
            }
        }
    } else if (blk < 1024) {
        int o = blk - 512;
#pragma unroll
        for (int c = 0; c < 4; c++) {
            const float* src = W1 + ((size_t)(c * H_ + o)) * H_;
            float bias = b1[c * H_ + o];
            float* dst = g_w1 + (size_t)o * K1P_ + c * S1_;
            for (int i = threadIdx.x; i < S1_; i += blockDim.x) {
                float v = (i < H_) ? src[i] : (i == H_ ? bias : 0.0f);
                dst[i] = to_tf32(v);
            }
        }
    } else {
        int o = blk - 1024;
        bool valid = (o < DOUT_);
#pragma unroll
        for (int c = 0; c < 4; c++) {
            const float* src = W2 + ((size_t)(c * DOUT_ + o)) * H_;
            float bias = valid ? b2[c * DOUT_ + o] : 0.0f;
            float* dst = g_w2 + (size_t)o * K1P_ + c * S1_;
            for (int i = threadIdx.x; i < S1_; i += blockDim.x) {
                float v = 0.0f;
                if (valid) v = (i < H_) ? src[i] : (i == H_ ? bias : 0.0f);
                dst[i] = to_tf32(v);
            }
        }
    }
}

// ---------------- tf32 mma.sync GEMM ----------------
// CTA 64x64, 8 warps (2M x 4N), warp tile 32x16, k-chunk 32, 3-stage cp.async.
// SMEM per stage: A(64x32) then B(64x32); each as 8x8 grid of (8r x 4c fp32)
// 128B matrices, row XOR-swizzled by k4 group.

#define NS 3

__device__ __forceinline__ void fill_stage(uint32_t sdst, const float* __restrict__ A,
                                           const float* __restrict__ Bw,
                                           int bm, int bn, int KP, int k0, int t) {
#pragma unroll
    for (int j = 0; j < 2; j++) {
        int f = t + j * 256;
        int m = f >> 3, k4 = f & 7;
        uint32_t off = (uint32_t)((((m >> 3) * 8 + k4) * 128) + (((m & 7) ^ k4) * 16));
        cp16(sdst + off, A + (size_t)(bm + m) * KP + k0 + k4 * 4);
        cp16(sdst + 8192u + off, Bw + (size_t)(bn + m) * KP + k0 + k4 * 4);
    }
}

template <int LAYER>
__global__ void __launch_bounds__(256) k_gemm(float* __restrict__ out_final) {
    constexpr int KP  = (LAYER == 0) ? K0P_ : K1P_;
    constexpr int NIT = KP / 32;
    const float* __restrict__ A  = (LAYER == 0) ? g_z0 : (LAYER == 1 ? g_z1 : g_z2);
    const float* __restrict__ Bw = (LAYER == 0) ? g_w0 : (LAYER == 1 ? g_w1 : g_w2);

    __shared__ float smem[NS][4096];   // [stage][A 64x32 | B 64x32]
    uint32_t sbase = smem_u32(smem);

    const int t = threadIdx.x, lane = t & 31, wid = t >> 5;
    const int wm = (wid >> 2) * 32, wn = (wid & 3) * 16;
    const int bm = blockIdx.y * 64, bn = blockIdx.x * 64;
    const int g = lane >> 3, r = lane & 7;
    const int ga = g & 1, gb = g >> 1;
    const int wm8 = wm >> 3, wn8 = wn >> 3;

    float acc[2][2][4] = {};

    fill_stage(sbase, A, Bw, bm, bn, KP, 0, t);
    cp_commit();
    fill_stage(sbase + 16384u, A, Bw, bm, bn, KP, 32, t);
    cp_commit();

#pragma unroll 1
    for (int it = 0; it < NIT; it++) {
        int s = it % NS;
        cp_wait<NS - 2>();
        __syncthreads();
        if (it + NS - 1 < NIT) {
            fill_stage(sbase + (uint32_t)((it + NS - 1) % NS) * 16384u,
                       A, Bw, bm, bn, KP, (it + NS - 1) * 32, t);
        }
        cp_commit();

        uint32_t sa  = sbase + (uint32_t)s * 16384u;
        uint32_t sbB = sa + 8192u;
#pragma unroll
        for (int ki2 = 0; ki2 < 4; ki2++) {
            int k4a = ki2 * 2 + gb;
            int k4b = ki2 * 2 + ga;
            uint32_t a0[4], a1[4], bb[4];
            ldsm4(a0, sa  + (uint32_t)((((wm8 + ga) * 8 + k4a) * 128) + ((r ^ k4a) * 16)));
            ldsm4(a1, sa  + (uint32_t)((((wm8 + 2 + ga) * 8 + k4a) * 128) + ((r ^ k4a) * 16)));
            ldsm4(bb, sbB + (uint32_t)((((wn8 + gb) * 8 + k4b) * 128) + ((r ^ k4b) * 16)));
            mma8(acc[0][0], a0, bb[0], bb[1]);
            mma8(acc[0][1], a0, bb[2], bb[3]);
            mma8(acc[1][0], a1, bb[0], bb[1]);
            mma8(acc[1][1], a1, bb[2], bb[3]);
        }
    }

    // ---- epilogue ----
    if (LAYER < 2) {
        float* __restrict__ zn = (LAYER == 0) ? g_z1 : g_z2;
#pragma unroll
        for (int mt = 0; mt < 2; mt++) {
            int m0 = bm + wm + mt * 16 + (lane >> 2);
            int m1 = m0 + 8;
            float4 cA = *(const float4*)&g_coef[m0 * 4];
            float4 cB = *(const float4*)&g_coef[m1 * 4];
            float ca[4] = {cA.x, cA.y, cA.z, cA.w};
            float cb[4] = {cB.x, cB.y, cB.z, cB.w};
#pragma unroll
            for (int nt = 0; nt < 2; nt++) {
                int n = bn + wn + nt * 8 + (lane & 3) * 2;
                float h00 = elu1(acc[mt][nt][0]);
                float h01 = elu1(acc[mt][nt][1]);
                float h10 = elu1(acc[mt][nt][2]);
                float h11 = elu1(acc[mt][nt][3]);
#pragma unroll
                for (int ct = 0; ct < 4; ct++) {
                    float2 v0 = make_float2(to_tf32(ca[ct] * h00), to_tf32(ca[ct] * h01));
                    float2 v1 = make_float2(to_tf32(cb[ct] * h10), to_tf32(cb[ct] * h11));
                    *(float2*)&zn[(size_t)m0 * K1P_ + ct * S1_ + n] = v0;
                    *(float2*)&zn[(size_t)m1 * K1P_ + ct * S1_ + n] = v1;
                }
            }
        }
    } else {
#pragma unroll
        for (int mt = 0; mt < 2; mt++) {
            int m0 = bm + wm + mt * 16 + (lane >> 2);
            int m1 = m0 + 8;
#pragma unroll
            for (int nt = 0; nt < 2; nt++) {
                int n = bn + wn + nt * 8 + (lane & 3) * 2;
                if (n < DOUT_) {
                    out_final[(size_t)m0 * DOUT_ + n] = acc[mt][nt][0];
                    out_final[(size_t)m1 * DOUT_ + n] = acc[mt][nt][2];
                }
                if (n + 1 < DOUT_) {
                    out_final[(size_t)m0 * DOUT_ + n + 1] = acc[mt][nt][1];
                    out_final[(size_t)m1 * DOUT_ + n + 1] = acc[mt][nt][3];
                }
            }
        }
    }
}

// ---------------- launch ----------------
extern "C" void kernel_launch(void* const* d_in, const int* in_sizes, int n_in,
                              void* d_out, int out_size) {
    const float* x  = (const float*)d_in[0];
    const float* W0 = (const float*)d_in[1];
    const float* W1 = (const float*)d_in[2];
    const float* W2 = (const float*)d_in[3];
    const float* b0 = (const float*)d_in[4];
    const float* b1 = (const float*)d_in[5];
    const float* b2 = (const float*)d_in[6];
    float* out = (float*)d_out;

    k_coef<<<4, 256>>>(x);
    k_wall<<<1344, 256>>>(W0, W1, W2, b0, b1, b2);
    k_z0<<<B_, 128>>>(x);

    k_gemm<0><<<dim3(8, 16), 256>>>(nullptr);
    k_gemm<1><<<dim3(8, 16), 256>>>(nullptr);
    k_gemm<2><<<dim3(5, 16), 256>>>(out);
}

// round 5
// speedup vs baseline: 1.3678x; 1.0887x over previous
#include <cuda_runtime.h>
#include <cstdint>
#include <math.h>

#define B_    1024
#define DIN_  343
#define DH_   342
#define H_    512
#define DOUT_ 311
#define NP2_  320

#define S0_   352            // per-control K stride, layer 0
#define K0P_  1408           // 4 * 352  (44 chunks of 32; 22 per split)
#define S1_   528            // 512 h + 1 bias + 15 pad
#define K1P_  2112           // 4 * 528  (66 chunks of 32; 33 per split)

// ---- scratch ----
__device__ float g_z0[B_ * K0P_];
__device__ float g_z1[B_ * K1P_];
__device__ float g_z2[B_ * K1P_];
__device__ float g_w0[H_ * K0P_];
__device__ float g_w1[H_ * K1P_];
__device__ float g_w2[NP2_ * K1P_];
__device__ float g_coef[B_ * 4];
__device__ float g_pA[B_ * H_];      // split-K partials (reused across layers)
__device__ float g_pB[B_ * H_];

// ---------------- helpers ----------------
__device__ __forceinline__ float to_tf32(float v) {
    uint32_t o; asm("cvt.rna.tf32.f32 %0, %1;" : "=r"(o) : "f"(v));
    return __uint_as_float(o);
}
__device__ __forceinline__ float elu1(float v) { return v > 0.0f ? v : expm1f(v); }

__device__ __forceinline__ uint32_t smem_u32(const void* p) {
    uint32_t a;
    asm("{ .reg .u64 t; cvta.to.shared.u64 t, %1; cvt.u32.u64 %0, t; }" : "=r"(a) : "l"(p));
    return a;
}
__device__ __forceinline__ void cp16(uint32_t dst, const float* src) {
    asm volatile("cp.async.cg.shared.global [%0], [%1], 16;" :: "r"(dst), "l"(src) : "memory");
}
__device__ __forceinline__ void cp_commit() { asm volatile("cp.async.commit_group;" ::: "memory"); }
template <int N> __device__ __forceinline__ void cp_wait() {
    asm volatile("cp.async.wait_group %0;" :: "n"(N) : "memory");
}
__device__ __forceinline__ void ldsm4(uint32_t* r, uint32_t addr) {
    asm volatile("ldmatrix.sync.aligned.m8n8.x4.shared.b16 {%0,%1,%2,%3}, [%4];"
                 : "=r"(r[0]), "=r"(r[1]), "=r"(r[2]), "=r"(r[3]) : "r"(addr));
}
__device__ __forceinline__ void mma8(float* c, const uint32_t* a, uint32_t b0, uint32_t b1) {
    asm volatile(
        "mma.sync.aligned.m16n8k8.row.col.f32.tf32.tf32.f32 "
        "{%0,%1,%2,%3}, {%4,%5,%6,%7}, {%8,%9}, {%0,%1,%2,%3};"
        : "+f"(c[0]), "+f"(c[1]), "+f"(c[2]), "+f"(c[3])
        : "r"(a[0]), "r"(a[1]), "r"(a[2]), "r"(a[3]), "r"(b0), "r"(b1));
}

// ---------------- prep kernels ----------------
__global__ void k_coef(const float* __restrict__ x) {
    int b = blockIdx.x * blockDim.x + threadIdx.x;
    if (b >= B_) return;
    float ps = 4.0f * x[b * DIN_ + (DIN_ - 1)];
    float mu = ps - floorf(ps);
    int   k1 = ((int)ps) & 3;
    float m2 = mu * mu, m3 = m2 * mu;
    float a0 = -0.5f * m3 +        m2 - 0.5f * mu;
    float a1 =  1.5f * m3 - 2.5f * m2 + 1.0f;
    float a2 = -1.5f * m3 + 2.0f * m2 + 0.5f * mu;
    float a3 =  0.5f * m3 - 0.5f * m2;
    float c[4];
    c[(k1 + 3) & 3] = a0;
    c[k1]           = a1;
    c[(k1 + 1) & 3] = a2;
    c[(k1 + 2) & 3] = a3;
#pragma unroll
    for (int j = 0; j < 4; j++) {
        g_coef[b * 4 + j] = c[j];
        float ct = to_tf32(c[j]);
        size_t base = (size_t)b * K1P_ + j * S1_;
        g_z1[base + 512] = ct;
        g_z2[base + 512] = ct;
#pragma unroll
        for (int p = 513; p < S1_; p++) { g_z1[base + p] = 0.0f; g_z2[base + p] = 0.0f; }
    }
}

__global__ void k_z0(const float* __restrict__ x) {
    int b = blockIdx.x;
    float4 cf = *(const float4*)&g_coef[b * 4];
    float cc[4] = {cf.x, cf.y, cf.z, cf.w};
    const float* xr = x + (size_t)b * DIN_;
    float* z = g_z0 + (size_t)b * K0P_;
    for (int i = threadIdx.x; i < S0_; i += blockDim.x) {
        float v0, v1, v2, v3;
        if (i < DH_) {
            float v = xr[i];
            v0 = to_tf32(cc[0] * v); v1 = to_tf32(cc[1] * v);
            v2 = to_tf32(cc[2] * v); v3 = to_tf32(cc[3] * v);
        } else if (i == DH_) {
            v0 = to_tf32(cc[0]); v1 = to_tf32(cc[1]);
            v2 = to_tf32(cc[2]); v3 = to_tf32(cc[3]);
        } else { v0 = v1 = v2 = v3 = 0.0f; }
        z[0 * S0_ + i] = v0; z[1 * S0_ + i] = v1;
        z[2 * S0_ + i] = v2; z[3 * S0_ + i] = v3;
    }
}

// one CTA per (o-row, control): grid (1344, 4), 128 threads
__global__ void k_wall(const float* __restrict__ W0, const float* __restrict__ W1,
                       const float* __restrict__ W2, const float* __restrict__ b0,
                       const float* __restrict__ b1, const float* __restrict__ b2) {
    int blk = blockIdx.x;
    int c = blockIdx.y;
    if (blk < 512) {
        int o = blk;
        const float* src = W0 + ((size_t)(c * H_ + o)) * DH_;
        float bias = b0[c * H_ + o];
        float* dst = g_w0 + (size_t)o * K0P_ + c * S0_;
        for (int i = threadIdx.x; i < S0_; i += blockDim.x) {
            float v = (i < DH_) ? src[i] : (i == DH_ ? bias : 0.0f);
            dst[i] = to_tf32(v);
        }
    } else if (blk < 1024) {
        int o = blk - 512;
        const float* src = W1 + ((size_t)(c * H_ + o)) * H_;
        float bias = b1[c * H_ + o];
        float* dst = g_w1 + (size_t)o * K1P_ + c * S1_;
        for (int i = threadIdx.x; i < S1_; i += blockDim.x) {
            float v = (i < H_) ? src[i] : (i == H_ ? bias : 0.0f);
            dst[i] = to_tf32(v);
        }
    } else {
        int o = blk - 1024;
        bool valid = (o < DOUT_);
        const float* src = W2 + ((size_t)(c * DOUT_ + o)) * H_;
        float bias = valid ? b2[c * DOUT_ + o] : 0.0f;
        float* dst = g_w2 + (size_t)o * K1P_ + c * S1_;
        for (int i = threadIdx.x; i < S1_; i += blockDim.x) {
            float v = 0.0f;
            if (valid) v = (i < H_) ? src[i] : (i == H_ ? bias : 0.0f);
            dst[i] = to_tf32(v);
        }
    }
}

// ---------------- tf32 mma.sync GEMM, split-K x2 ----------------
// CTA 64x64, 8 warps (2M x 4N), warp tile 32x16, k-chunk 32, 3-stage cp.async.
// blockIdx.z = K-split; partials to g_pA / g_pB, summed in k_ep.

#define NS 3

__device__ __forceinline__ void fill_stage(uint32_t sdst, const float* __restrict__ A,
                                           const float* __restrict__ Bw,
                                           int bm, int bn, int KP, int k0, int t) {
#pragma unroll
    for (int j = 0; j < 2; j++) {
        int f = t + j * 256;
        int m = f >> 3, k4 = f & 7;
        uint32_t off = (uint32_t)((((m >> 3) * 8 + k4) * 128) + (((m & 7) ^ k4) * 16));
        cp16(sdst + off, A + (size_t)(bm + m) * KP + k0 + k4 * 4);
        cp16(sdst + 8192u + off, Bw + (size_t)(bn + m) * KP + k0 + k4 * 4);
    }
}

template <int LAYER>
__global__ void __launch_bounds__(256) k_gemm() {
    constexpr int KP    = (LAYER == 0) ? K0P_ : K1P_;
    constexpr int KHALF = KP / 2;
    constexpr int NIT   = KHALF / 32;
    constexpr int NP    = (LAYER == 2) ? NP2_ : H_;
    const float* __restrict__ A  = (LAYER == 0) ? g_z0 : (LAYER == 1 ? g_z1 : g_z2);
    const float* __restrict__ Bw = (LAYER == 0) ? g_w0 : (LAYER == 1 ? g_w1 : g_w2);

    __shared__ float smem[NS][4096];
    uint32_t sbase = smem_u32(smem);

    const int t = threadIdx.x, lane = t & 31, wid = t >> 5;
    const int wm = (wid >> 2) * 32, wn = (wid & 3) * 16;
    const int bm = blockIdx.y * 64, bn = blockIdx.x * 64;
    const int kbase = blockIdx.z * KHALF;
    float* __restrict__ dst = blockIdx.z ? g_pB : g_pA;
    const int g = lane >> 3, r = lane & 7;
    const int ga = g & 1, gb = g >> 1;
    const int wm8 = wm >> 3, wn8 = wn >> 3;

    float acc[2][2][4] = {};

    fill_stage(sbase, A, Bw, bm, bn, KP, kbase, t);
    cp_commit();
    fill_stage(sbase + 16384u, A, Bw, bm, bn, KP, kbase + 32, t);
    cp_commit();

#pragma unroll 1
    for (int it = 0; it < NIT; it++) {
        int s = it % NS;
        cp_wait<NS - 2>();
        __syncthreads();
        if (it + NS - 1 < NIT) {
            fill_stage(sbase + (uint32_t)((it + NS - 1) % NS) * 16384u,
                       A, Bw, bm, bn, KP, kbase + (it + NS - 1) * 32, t);
        }
        cp_commit();

        uint32_t sa  = sbase + (uint32_t)s * 16384u;
        uint32_t sbB = sa + 8192u;
#pragma unroll
        for (int ki2 = 0; ki2 < 4; ki2++) {
            int k4a = ki2 * 2 + gb;
            int k4b = ki2 * 2 + ga;
            uint32_t a0[4], a1[4], bb[4];
            ldsm4(a0, sa  + (uint32_t)((((wm8 + ga) * 8 + k4a) * 128) + ((r ^ k4a) * 16)));
            ldsm4(a1, sa  + (uint32_t)((((wm8 + 2 + ga) * 8 + k4a) * 128) + ((r ^ k4a) * 16)));
            ldsm4(bb, sbB + (uint32_t)((((wn8 + gb) * 8 + k4b) * 128) + ((r ^ k4b) * 16)));
            mma8(acc[0][0], a0, bb[0], bb[1]);
            mma8(acc[0][1], a0, bb[2], bb[3]);
            mma8(acc[1][0], a1, bb[0], bb[1]);
            mma8(acc[1][1], a1, bb[2], bb[3]);
        }
    }

    // store raw partials
#pragma unroll
    for (int mt = 0; mt < 2; mt++) {
        int m0 = bm + wm + mt * 16 + (lane >> 2);
        int m1 = m0 + 8;
#pragma unroll
        for (int nt = 0; nt < 2; nt++) {
            int n = bn + wn + nt * 8 + (lane & 3) * 2;
            *(float2*)&dst[(size_t)m0 * NP + n] = make_float2(acc[mt][nt][0], acc[mt][nt][1]);
            *(float2*)&dst[(size_t)m1 * NP + n] = make_float2(acc[mt][nt][2], acc[mt][nt][3]);
        }
    }
}

// ---- epilogue: sum partials, ELU + coef scatter (or final store) ----
template <int LAYER>
__global__ void k_ep(float* __restrict__ out_final) {
    int b = blockIdx.x;
    int tx = threadIdx.x;
    if (LAYER < 2) {
        float4 cf = *(const float4*)&g_coef[b * 4];
        float cc[4] = {cf.x, cf.y, cf.z, cf.w};
        const float* pa = g_pA + (size_t)b * H_;
        const float* pb = g_pB + (size_t)b * H_;
        float* zn = ((LAYER == 0) ? g_z1 : g_z2) + (size_t)b * K1P_;
        int n = tx * 4;
        float4 va = *(const float4*)(pa + n);
        float4 vb = *(const float4*)(pb + n);
        float h0 = elu1(va.x + vb.x), h1 = elu1(va.y + vb.y);
        float h2 = elu1(va.z + vb.z), h3 = elu1(va.w + vb.w);
#pragma unroll
        for (int ct = 0; ct < 4; ct++) {
            float4 w = make_float4(to_tf32(cc[ct] * h0), to_tf32(cc[ct] * h1),
                                   to_tf32(cc[ct] * h2), to_tf32(cc[ct] * h3));
            *(float4*)(zn + ct * S1_ + n) = w;
        }
    } else {
        const float* pa = g_pA + (size_t)b * NP2_;
        const float* pb = g_pB + (size_t)b * NP2_;
        float* o = out_final + (size_t)b * DOUT_;
        for (int n = tx; n < DOUT_; n += blockDim.x)
            o[n] = pa[n] + pb[n];
    }
}

// ---------------- launch ----------------
extern "C" void kernel_launch(void* const* d_in, const int* in_sizes, int n_in,
                              void* d_out, int out_size) {
    const float* x  = (const float*)d_in[0];
    const float* W0 = (const float*)d_in[1];
    const float* W1 = (const float*)d_in[2];
    const float* W2 = (const float*)d_in[3];
    const float* b0 = (const float*)d_in[4];
    const float* b1 = (const float*)d_in[5];
    const float* b2 = (const float*)d_in[6];
    float* out = (float*)d_out;

    k_coef<<<4, 256>>>(x);
    k_wall<<<dim3(1344, 4), 128>>>(W0, W1, W2, b0, b1, b2);
    k_z0<<<B_, 128>>>(x);

    k_gemm<0><<<dim3(8, 16, 2), 256>>>();
    k_ep<0><<<B_, 128>>>(nullptr);
    k_gemm<1><<<dim3(8, 16, 2), 256>>>();
    k_ep<1><<<B_, 128>>>(nullptr);
    k_gemm<2><<<dim3(5, 16, 2), 256>>>();
    k_ep<2><<<B_, 128>>>(out);
}